// round 2
// baseline (speedup 1.0000x reference)
#include <cuda_runtime.h>
#include <cstdint>

#define N_NODES 50000
#define E_EDGES 500000
#define H_DIM   128
#define ROW_F   512          // 4 channels * 128 floats per node

// Scratch: aggregated neighbor features, same layout as x: (N, 4, H)
__device__ float g_agg[(size_t)N_NODES * ROW_F];
// Flag: 1 if edge_index is stored as int64, 0 if int32
__device__ int g_is64;

// ---------------------------------------------------------------------------
// Phase 0: detect edge_index dtype.
// If storage is int64 (values < 2^31), every odd int32 word is 0.
// If storage is int32, odd words are real edge indices (~0 prob of all-zero).
// ---------------------------------------------------------------------------
__global__ void detect_dtype_kernel(const int* __restrict__ ei32) {
    int all_zero = 1;
    for (int i = 0; i < 128; i++) {
        if (ei32[2 * i + 1] != 0) { all_zero = 0; break; }
    }
    g_is64 = all_zero;
}

// ---------------------------------------------------------------------------
// Phase 1: zero the aggregation buffer (102.4 MB)
// ---------------------------------------------------------------------------
__global__ void zero_agg_kernel() {
    size_t i = (size_t)blockIdx.x * blockDim.x + threadIdx.x;
    const size_t n4 = (size_t)N_NODES * ROW_F / 4;   // 6.4M float4
    if (i < n4) {
        ((float4*)g_agg)[i] = make_float4(0.f, 0.f, 0.f, 0.f);
    }
}

// ---------------------------------------------------------------------------
// Phase 2: edge aggregation. agg[row] += x[col] (512 floats per edge).
// 128 threads per edge, each thread moves one float4 via vector red.
// ---------------------------------------------------------------------------
__global__ __launch_bounds__(256)
void edge_agg_kernel(const float* __restrict__ x,
                     const void* __restrict__ ei_raw) {
    int e    = blockIdx.x * 2 + (threadIdx.x >> 7);
    int lane = threadIdx.x & 127;
    if (e >= E_EDGES) return;

    long long row, col;
    if (g_is64) {
        const long long* ei = (const long long*)ei_raw;
        row = ei[e];
        col = ei[(size_t)E_EDGES + e];
    } else {
        const int* ei = (const int*)ei_raw;
        row = ei[e];
        col = ei[(size_t)E_EDGES + e];
    }

    float4 v = __ldg((const float4*)(x + (size_t)col * ROW_F) + lane);
    float* dst = g_agg + (size_t)row * ROW_F + lane * 4;
    asm volatile("red.global.add.v4.f32 [%0], {%1, %2, %3, %4};"
                 :: "l"(dst), "f"(v.x), "f"(v.y), "f"(v.z), "f"(v.w)
                 : "memory");
}

// ---------------------------------------------------------------------------
// Phase 3: per-node transform.
//   out[n,c,:] = x[n,c,:] @ Wroot_c^T + agg[n,c,:] @ Wrel_c^T (+ b if c==0)
// Cast as GEMM with K=256 (stacked [x_row, agg_row]) against a 128x256
// stacked weight, per channel class. Block: 64 nodes x 128 outs.
// ---------------------------------------------------------------------------
#define BM       64
#define ASTRIDE  260   // 256 + pad, multiple of 4 for float4 stores

__global__ __launch_bounds__(256, 1)
void transform_kernel(const float* __restrict__ x,
                      const float* __restrict__ Wsrel,
                      const float* __restrict__ Wsroot,
                      const float* __restrict__ bsr,
                      const float* __restrict__ Wvrel,
                      const float* __restrict__ Wvroot,
                      float* __restrict__ out) {
    extern __shared__ float sm[];
    float* Wt = sm;                      // [256][128]   transposed stacked weight
    float* As = sm + 256 * 128;          // [64][ASTRIDE]

    const int c     = blockIdx.y;        // channel 0..3
    const int node0 = blockIdx.x * BM;
    const int tid   = threadIdx.x;

    const float* root = (c == 0) ? Wsroot : Wvroot;
    const float* rel  = (c == 0) ? Wsrel  : Wvrel;
    const float* agg  = g_agg;

    // Load stacked weight transposed: Wt[k*128 + o] = W[o, k(-128)]
    for (int idx = tid; idx < 256 * 128; idx += 256) {
        int k = idx >> 7;
        int o = idx & 127;
        float w = (k < 128) ? __ldg(root + o * 128 + k)
                            : __ldg(rel  + o * 128 + (k - 128));
        Wt[idx] = w;
    }

    // Load A tile: 64 rows x 256 (first 128 from x, next 128 from agg)
    for (int idx = tid; idx < BM * 64; idx += 256) {   // 64 float4 per row
        int m = idx >> 6;
        int q = idx & 63;                              // float4 index within 256
        int node = node0 + m;
        float4 v = make_float4(0.f, 0.f, 0.f, 0.f);
        if (node < N_NODES) {
            size_t base = (size_t)node * ROW_F + (size_t)c * H_DIM;
            v = (q < 32) ? __ldg((const float4*)(x   + base) + q)
                         : __ldg((const float4*)(agg + base) + (q - 32));
        }
        *(float4*)(As + m * ASTRIDE + q * 4) = v;
    }
    __syncthreads();

    const int tx = tid & 15;   // output cols 8*tx .. 8*tx+7
    const int ty = tid >> 4;   // rows 4*ty .. 4*ty+3

    float acc[4][8];
    #pragma unroll
    for (int i = 0; i < 4; i++)
        #pragma unroll
        for (int j = 0; j < 8; j++) acc[i][j] = 0.f;

    const float* a0p = As + (4 * ty + 0) * ASTRIDE;
    const float* a1p = As + (4 * ty + 1) * ASTRIDE;
    const float* a2p = As + (4 * ty + 2) * ASTRIDE;
    const float* a3p = As + (4 * ty + 3) * ASTRIDE;
    const float* wp  = Wt + tx * 8;

    #pragma unroll 4
    for (int k = 0; k < 256; k++) {
        float4 w0 = *(const float4*)(wp + (size_t)k * 128);
        float4 w1 = *(const float4*)(wp + (size_t)k * 128 + 4);
        float a[4] = { a0p[k], a1p[k], a2p[k], a3p[k] };
        float w[8] = { w0.x, w0.y, w0.z, w0.w, w1.x, w1.y, w1.z, w1.w };
        #pragma unroll
        for (int i = 0; i < 4; i++)
            #pragma unroll
            for (int j = 0; j < 8; j++)
                acc[i][j] += a[i] * w[j];
    }

    // Bias (scalar channel only)
    float bias[8];
    #pragma unroll
    for (int j = 0; j < 8; j++)
        bias[j] = (c == 0) ? __ldg(bsr + tx * 8 + j) : 0.f;

    #pragma unroll
    for (int i = 0; i < 4; i++) {
        int node = node0 + 4 * ty + i;
        if (node < N_NODES) {
            float* op = out + (size_t)node * ROW_F + (size_t)c * H_DIM + tx * 8;
            float4 o0 = make_float4(acc[i][0] + bias[0], acc[i][1] + bias[1],
                                    acc[i][2] + bias[2], acc[i][3] + bias[3]);
            float4 o1 = make_float4(acc[i][4] + bias[4], acc[i][5] + bias[5],
                                    acc[i][6] + bias[6], acc[i][7] + bias[7]);
            *(float4*)(op)     = o0;
            *(float4*)(op + 4) = o1;
        }
    }
}

// ---------------------------------------------------------------------------
// Launch
// ---------------------------------------------------------------------------
extern "C" void kernel_launch(void* const* d_in, const int* in_sizes, int n_in,
                              void* d_out, int out_size) {
    const float* x      = (const float*)d_in[0];
    const void*  ei     = d_in[1];
    const float* Wsrel  = (const float*)d_in[2];
    const float* Wsroot = (const float*)d_in[3];
    const float* bsr    = (const float*)d_in[4];
    const float* Wvrel  = (const float*)d_in[5];
    const float* Wvroot = (const float*)d_in[6];
    float*       out    = (float*)d_out;

    const int smem_bytes = (256 * 128 + BM * ASTRIDE) * sizeof(float); // 197632
    cudaFuncSetAttribute(transform_kernel,
                         cudaFuncAttributeMaxDynamicSharedMemorySize, smem_bytes);

    // Phase 0: detect index dtype (int32 vs int64)
    detect_dtype_kernel<<<1, 1>>>((const int*)ei);

    // Phase 1: zero agg
    {
        const size_t n4 = (size_t)N_NODES * ROW_F / 4;
        int blocks = (int)((n4 + 255) / 256);
        zero_agg_kernel<<<blocks, 256>>>();
    }

    // Phase 2: edge aggregation (2 edges per 256-thread block)
    {
        int blocks = (E_EDGES + 1) / 2;
        edge_agg_kernel<<<blocks, 256>>>(x, ei);
    }

    // Phase 3: transform
    {
        dim3 grid((N_NODES + BM - 1) / BM, 4);
        transform_kernel<<<grid, 256, smem_bytes>>>(x, Wsrel, Wsroot, bsr,
                                                    Wvrel, Wvroot, out);
    }
}

// round 3
// speedup vs baseline: 2.0187x; 2.0187x over previous
#include <cuda_runtime.h>
#include <cstdint>

#define N_NODES 50000
#define E_EDGES 500000
#define H_DIM   128
#define ROW_F   512          // 4 channels * 128 floats per node

typedef unsigned long long u64;

// Scratch: aggregated neighbor features, same layout as x: (N, 4, H)
__device__ float g_agg[(size_t)N_NODES * ROW_F];
// Stacked transposed weights: [c][k(256)][o(128)] ; k<128 -> root^T, k>=128 -> rel^T
__device__ float g_Wt[4 * 256 * 128];
// Flag: 1 if edge_index is stored as int64, 0 if int32
__device__ int g_is64;

// ---------------------------------------------------------------------------
// packed f32x2 helpers (SASS FFMA2 — 2x fp32 FMA throughput, PTX-only)
// ---------------------------------------------------------------------------
__device__ __forceinline__ u64 pk2(float lo, float hi) {
    u64 r; asm("mov.b64 %0, {%1, %2};" : "=l"(r) : "f"(lo), "f"(hi)); return r;
}
__device__ __forceinline__ void upk2(u64 v, float& lo, float& hi) {
    asm("mov.b64 {%0, %1}, %2;" : "=f"(lo), "=f"(hi) : "l"(v));
}
__device__ __forceinline__ void ffma2(u64& d, u64 a, u64 b) {
    asm("fma.rn.f32x2 %0, %1, %2, %0;" : "+l"(d) : "l"(a), "l"(b));
}

// ---------------------------------------------------------------------------
// Phase 0a: detect edge_index dtype (int64 stored vs int32 stored)
// ---------------------------------------------------------------------------
__global__ void detect_dtype_kernel(const int* __restrict__ ei32) {
    int all_zero = 1;
    for (int i = 0; i < 128; i++) {
        if (ei32[2 * i + 1] != 0) { all_zero = 0; break; }
    }
    g_is64 = all_zero;
}

// ---------------------------------------------------------------------------
// Phase 0b: build stacked transposed weights g_Wt[c][k][o]
// ---------------------------------------------------------------------------
__global__ void prep_weights_kernel(const float* __restrict__ Wsrel,
                                    const float* __restrict__ Wsroot,
                                    const float* __restrict__ Wvrel,
                                    const float* __restrict__ Wvroot) {
    int c = blockIdx.y;          // 0..3
    int k = blockIdx.x;          // 0..255
    int o = threadIdx.x;         // 0..127
    const float* root = (c == 0) ? Wsroot : Wvroot;
    const float* rel  = (c == 0) ? Wsrel  : Wvrel;
    float v = (k < 128) ? __ldg(root + o * 128 + k)
                        : __ldg(rel  + o * 128 + (k - 128));
    g_Wt[((size_t)c * 256 + k) * 128 + o] = v;
}

// ---------------------------------------------------------------------------
// Phase 1: zero the aggregation buffer (102.4 MB)
// ---------------------------------------------------------------------------
__global__ void zero_agg_kernel() {
    size_t i = (size_t)blockIdx.x * blockDim.x + threadIdx.x;
    const size_t n4 = (size_t)N_NODES * ROW_F / 4;
    if (i < n4) ((float4*)g_agg)[i] = make_float4(0.f, 0.f, 0.f, 0.f);
}

// ---------------------------------------------------------------------------
// Phase 2: edge aggregation. agg[row] += x[col] (512 floats per edge).
// ---------------------------------------------------------------------------
__global__ __launch_bounds__(256)
void edge_agg_kernel(const float* __restrict__ x,
                     const void* __restrict__ ei_raw) {
    int e    = blockIdx.x * 2 + (threadIdx.x >> 7);
    int lane = threadIdx.x & 127;
    if (e >= E_EDGES) return;

    long long row, col;
    if (g_is64) {
        const long long* ei = (const long long*)ei_raw;
        row = ei[e];
        col = ei[(size_t)E_EDGES + e];
    } else {
        const int* ei = (const int*)ei_raw;
        row = ei[e];
        col = ei[(size_t)E_EDGES + e];
    }

    float4 v = __ldg((const float4*)(x + (size_t)col * ROW_F) + lane);
    float* dst = g_agg + (size_t)row * ROW_F + lane * 4;
    asm volatile("red.global.add.v4.f32 [%0], {%1, %2, %3, %4};"
                 :: "l"(dst), "f"(v.x), "f"(v.y), "f"(v.z), "f"(v.w)
                 : "memory");
}

// ---------------------------------------------------------------------------
// Phase 3: per-node transform, K=256 stacked GEMM, FFMA2, 128x128 block.
//   BM=128 nodes, BN=128 outs, 256 threads, thread tile 8m x 8n.
//   K chunked 4 x 64; smem = Ws[64][128] + As[128][68] = 66 KB -> 2 CTAs/SM.
// ---------------------------------------------------------------------------
#define BM    128
#define KC    64
#define ASTR  68

__global__ __launch_bounds__(256, 2)
void transform_kernel(const float* __restrict__ x,
                      const float* __restrict__ bsr,
                      float* __restrict__ out) {
    extern __shared__ float sm[];
    float* Ws = sm;                    // [KC][128]
    float* As = sm + KC * 128;         // [BM][ASTR]

    const int c     = blockIdx.y;
    const int node0 = blockIdx.x * BM;
    const int tid   = threadIdx.x;
    const int tx    = tid & 15;        // n-tile: cols tx*8 .. +7
    const int ty    = tid >> 4;        // m-tile: rows 8*ty .. +7

    u64 acc2[8][4];
    #pragma unroll
    for (int i = 0; i < 8; i++)
        #pragma unroll
        for (int j = 0; j < 4; j++) acc2[i][j] = 0ULL;

    const float* agg = g_agg;

    for (int kc = 0; kc < 4; kc++) {
        // ---- load W chunk: 64 k-rows x 128 outs, fully coalesced ----
        {
            const float4* src = (const float4*)(g_Wt + ((size_t)c * 256 + kc * KC) * 128);
            float4* dst = (float4*)Ws;
            #pragma unroll
            for (int it = 0; it < 8; it++)
                dst[tid + it * 256] = __ldg(src + tid + it * 256);
        }
        // ---- load A chunk: 128 nodes x 64 k ----
        {
            const float* srcbase = (kc < 2) ? x : agg;
            const int koff = (kc & 1) * KC + c * H_DIM;
            #pragma unroll
            for (int it = 0; it < 8; it++) {
                int idx = tid + it * 256;          // 0..2047
                int q = idx & 15;                  // float4 within row
                int m = idx >> 4;                  // node row 0..127
                int node = node0 + m;
                float4 v = make_float4(0.f, 0.f, 0.f, 0.f);
                if (node < N_NODES)
                    v = __ldg((const float4*)(srcbase + (size_t)node * ROW_F + koff) + q);
                *(float4*)(As + m * ASTR + q * 4) = v;
            }
        }
        __syncthreads();

        // ---- compute ----
        #pragma unroll 8
        for (int k = 0; k < KC; k++) {
            const float* wr = Ws + k * 128 + tx * 8;
            ulonglong2 wa = *(const ulonglong2*)(wr);
            ulonglong2 wb = *(const ulonglong2*)(wr + 4);
            u64 wv0 = wa.x, wv1 = wa.y, wv2 = wb.x, wv3 = wb.y;
            #pragma unroll
            for (int i = 0; i < 8; i++) {
                float a = As[(8 * ty + i) * ASTR + k];
                u64 av = pk2(a, a);
                ffma2(acc2[i][0], av, wv0);
                ffma2(acc2[i][1], av, wv1);
                ffma2(acc2[i][2], av, wv2);
                ffma2(acc2[i][3], av, wv3);
            }
        }
        __syncthreads();
    }

    // ---- epilogue ----
    float bias[8];
    #pragma unroll
    for (int j = 0; j < 8; j++)
        bias[j] = (c == 0) ? __ldg(bsr + tx * 8 + j) : 0.f;

    #pragma unroll
    for (int i = 0; i < 8; i++) {
        int node = node0 + 8 * ty + i;
        if (node < N_NODES) {
            float r[8];
            #pragma unroll
            for (int j = 0; j < 4; j++)
                upk2(acc2[i][j], r[2 * j], r[2 * j + 1]);
            float* op = out + (size_t)node * ROW_F + (size_t)c * H_DIM + tx * 8;
            *(float4*)(op)     = make_float4(r[0] + bias[0], r[1] + bias[1],
                                             r[2] + bias[2], r[3] + bias[3]);
            *(float4*)(op + 4) = make_float4(r[4] + bias[4], r[5] + bias[5],
                                             r[6] + bias[6], r[7] + bias[7]);
        }
    }
}

// ---------------------------------------------------------------------------
// Launch
// ---------------------------------------------------------------------------
extern "C" void kernel_launch(void* const* d_in, const int* in_sizes, int n_in,
                              void* d_out, int out_size) {
    const float* x      = (const float*)d_in[0];
    const void*  ei     = d_in[1];
    const float* Wsrel  = (const float*)d_in[2];
    const float* Wsroot = (const float*)d_in[3];
    const float* bsr    = (const float*)d_in[4];
    const float* Wvrel  = (const float*)d_in[5];
    const float* Wvroot = (const float*)d_in[6];
    float*       out    = (float*)d_out;

    const int smem_bytes = (KC * 128 + BM * ASTR) * sizeof(float);  // 67584
    cudaFuncSetAttribute(transform_kernel,
                         cudaFuncAttributeMaxDynamicSharedMemorySize, smem_bytes);

    // Phase 0: dtype detect + weight prep
    detect_dtype_kernel<<<1, 1>>>((const int*)ei);
    {
        dim3 grid(256, 4);
        prep_weights_kernel<<<grid, 128>>>(Wsrel, Wsroot, Wvrel, Wvroot);
    }

    // Phase 1: zero agg
    {
        const size_t n4 = (size_t)N_NODES * ROW_F / 4;
        int blocks = (int)((n4 + 255) / 256);
        zero_agg_kernel<<<blocks, 256>>>();
    }

    // Phase 2: edge aggregation
    {
        int blocks = (E_EDGES + 1) / 2;
        edge_agg_kernel<<<blocks, 256>>>(x, ei);
    }

    // Phase 3: transform
    {
        dim3 grid((N_NODES + BM - 1) / BM, 4);
        transform_kernel<<<grid, 256, smem_bytes>>>(x, bsr, out);
    }
}

// round 4
// speedup vs baseline: 2.5963x; 1.2861x over previous
#include <cuda_runtime.h>
#include <cstdint>

#define N_NODES 50000
#define E_EDGES 500000
#define H_DIM   128
#define ROW_F   512          // 4 channels * 128 floats per node

typedef unsigned long long u64;

// Scratch
__device__ float g_agg[(size_t)N_NODES * ROW_F];     // aggregated neighbor feats
__device__ float g_Wt[4 * 256 * 128];                // stacked transposed weights
__device__ int   g_is64;                             // edge dtype flag
__device__ int   g_cnt[N_NODES];                     // per-row edge counts
__device__ int   g_off[N_NODES + 1];                 // CSR offsets
__device__ int   g_cur[N_NODES];                     // scatter cursors
__device__ int   g_cols[E_EDGES];                    // CSR column indices

// ---------------------------------------------------------------------------
// packed f32x2 helpers (SASS FFMA2)
// ---------------------------------------------------------------------------
__device__ __forceinline__ u64 pk2(float lo, float hi) {
    u64 r; asm("mov.b64 %0, {%1, %2};" : "=l"(r) : "f"(lo), "f"(hi)); return r;
}
__device__ __forceinline__ void upk2(u64 v, float& lo, float& hi) {
    asm("mov.b64 {%0, %1}, %2;" : "=f"(lo), "=f"(hi) : "l"(v));
}
__device__ __forceinline__ void ffma2(u64& d, u64 a, u64 b) {
    asm("fma.rn.f32x2 %0, %1, %2, %0;" : "+l"(d) : "l"(a), "l"(b));
}

// ---------------------------------------------------------------------------
// edge index fetch with dtype branch
// ---------------------------------------------------------------------------
__device__ __forceinline__ int edge_idx(const void* ei_raw, size_t i) {
    if (g_is64) return (int)((const long long*)ei_raw)[i];
    return ((const int*)ei_raw)[i];
}

// ---------------------------------------------------------------------------
// Phase 0a: detect edge_index dtype (int64 stored vs int32 stored)
// ---------------------------------------------------------------------------
__global__ void detect_dtype_kernel(const int* __restrict__ ei32) {
    int all_zero = 1;
    for (int i = 0; i < 128; i++) {
        if (ei32[2 * i + 1] != 0) { all_zero = 0; break; }
    }
    g_is64 = all_zero;
}

// ---------------------------------------------------------------------------
// Phase 0b: build stacked transposed weights g_Wt[c][k][o]
// ---------------------------------------------------------------------------
__global__ void prep_weights_kernel(const float* __restrict__ Wsrel,
                                    const float* __restrict__ Wsroot,
                                    const float* __restrict__ Wvrel,
                                    const float* __restrict__ Wvroot) {
    int c = blockIdx.y;
    int k = blockIdx.x;
    int o = threadIdx.x;
    const float* root = (c == 0) ? Wsroot : Wvroot;
    const float* rel  = (c == 0) ? Wsrel  : Wvrel;
    float v = (k < 128) ? __ldg(root + o * 128 + k)
                        : __ldg(rel  + o * 128 + (k - 128));
    g_Wt[((size_t)c * 256 + k) * 128 + o] = v;
}

// ---------------------------------------------------------------------------
// CSR build: zero counts -> histogram -> scan -> scatter
// ---------------------------------------------------------------------------
__global__ void zero_cnt_kernel() {
    int i = blockIdx.x * blockDim.x + threadIdx.x;
    if (i < N_NODES) g_cnt[i] = 0;
}

__global__ __launch_bounds__(256)
void hist_kernel(const void* __restrict__ ei_raw) {
    int e = blockIdx.x * blockDim.x + threadIdx.x;
    if (e < E_EDGES) {
        int row = edge_idx(ei_raw, e);
        atomicAdd(&g_cnt[row], 1);
    }
}

__global__ __launch_bounds__(1024)
void scan_kernel() {
    __shared__ int s[1024];
    __shared__ int carry_s;
    int tid = threadIdx.x;
    if (tid == 0) carry_s = 0;
    __syncthreads();
    for (int base = 0; base < N_NODES; base += 1024) {
        int i = base + tid;
        int v = (i < N_NODES) ? g_cnt[i] : 0;
        s[tid] = v;
        __syncthreads();
        #pragma unroll
        for (int d = 1; d < 1024; d <<= 1) {
            int t = (tid >= d) ? s[tid - d] : 0;
            __syncthreads();
            s[tid] += t;
            __syncthreads();
        }
        int excl = s[tid] - v;
        int carry = carry_s;
        if (i < N_NODES) {
            g_off[i] = carry + excl;
            g_cur[i] = carry + excl;
        }
        int total = s[1023];
        __syncthreads();
        if (tid == 0) carry_s = carry + total;
        __syncthreads();
    }
    if (tid == 0) g_off[N_NODES] = carry_s;
}

__global__ __launch_bounds__(256)
void scatter_kernel(const void* __restrict__ ei_raw) {
    int e = blockIdx.x * blockDim.x + threadIdx.x;
    if (e < E_EDGES) {
        int row = edge_idx(ei_raw, e);
        int col = edge_idx(ei_raw, (size_t)E_EDGES + e);
        int pos = atomicAdd(&g_cur[row], 1);
        g_cols[pos] = col;
    }
}

// ---------------------------------------------------------------------------
// Phase 2: CSR aggregation. agg[n] = sum_{col in adj(n)} x[col]. No atomics.
// 128 threads per node (each owns one float4 slice of the 512-float row).
// ---------------------------------------------------------------------------
__global__ __launch_bounds__(256)
void csr_agg_kernel(const float* __restrict__ x) {
    int node = blockIdx.x * 2 + (threadIdx.x >> 7);
    int lane = threadIdx.x & 127;
    if (node >= N_NODES) return;

    int beg = __ldg(&g_off[node]);
    int end = __ldg(&g_off[node + 1]);

    float4 acc = make_float4(0.f, 0.f, 0.f, 0.f);
    for (int j = beg; j < end; j++) {
        int col = __ldg(&g_cols[j]);
        float4 v = __ldg((const float4*)(x + (size_t)col * ROW_F) + lane);
        acc.x += v.x; acc.y += v.y; acc.z += v.z; acc.w += v.w;
    }
    ((float4*)(g_agg + (size_t)node * ROW_F))[lane] = acc;
}

// ---------------------------------------------------------------------------
// Phase 3: per-node transform, K=256 stacked GEMM, FFMA2, 128x128 block.
// ---------------------------------------------------------------------------
#define BM    128
#define KC    64
#define ASTR  68

__global__ __launch_bounds__(256, 2)
void transform_kernel(const float* __restrict__ x,
                      const float* __restrict__ bsr,
                      float* __restrict__ out) {
    extern __shared__ float sm[];
    float* Ws = sm;                    // [KC][128]
    float* As = sm + KC * 128;         // [BM][ASTR]

    const int c     = blockIdx.y;
    const int node0 = blockIdx.x * BM;
    const int tid   = threadIdx.x;
    const int tx    = tid & 15;
    const int ty    = tid >> 4;

    u64 acc2[8][4];
    #pragma unroll
    for (int i = 0; i < 8; i++)
        #pragma unroll
        for (int j = 0; j < 4; j++) acc2[i][j] = 0ULL;

    const float* agg = g_agg;

    for (int kc = 0; kc < 4; kc++) {
        {
            const float4* src = (const float4*)(g_Wt + ((size_t)c * 256 + kc * KC) * 128);
            float4* dst = (float4*)Ws;
            #pragma unroll
            for (int it = 0; it < 8; it++)
                dst[tid + it * 256] = __ldg(src + tid + it * 256);
        }
        {
            const float* srcbase = (kc < 2) ? x : agg;
            const int koff = (kc & 1) * KC + c * H_DIM;
            #pragma unroll
            for (int it = 0; it < 8; it++) {
                int idx = tid + it * 256;
                int q = idx & 15;
                int m = idx >> 4;
                int node = node0 + m;
                float4 v = make_float4(0.f, 0.f, 0.f, 0.f);
                if (node < N_NODES)
                    v = __ldg((const float4*)(srcbase + (size_t)node * ROW_F + koff) + q);
                *(float4*)(As + m * ASTR + q * 4) = v;
            }
        }
        __syncthreads();

        #pragma unroll 8
        for (int k = 0; k < KC; k++) {
            const float* wr = Ws + k * 128 + tx * 8;
            ulonglong2 wa = *(const ulonglong2*)(wr);
            ulonglong2 wb = *(const ulonglong2*)(wr + 4);
            u64 wv0 = wa.x, wv1 = wa.y, wv2 = wb.x, wv3 = wb.y;
            #pragma unroll
            for (int i = 0; i < 8; i++) {
                float a = As[(8 * ty + i) * ASTR + k];
                u64 av = pk2(a, a);
                ffma2(acc2[i][0], av, wv0);
                ffma2(acc2[i][1], av, wv1);
                ffma2(acc2[i][2], av, wv2);
                ffma2(acc2[i][3], av, wv3);
            }
        }
        __syncthreads();
    }

    float bias[8];
    #pragma unroll
    for (int j = 0; j < 8; j++)
        bias[j] = (c == 0) ? __ldg(bsr + tx * 8 + j) : 0.f;

    #pragma unroll
    for (int i = 0; i < 8; i++) {
        int node = node0 + 8 * ty + i;
        if (node < N_NODES) {
            float r[8];
            #pragma unroll
            for (int j = 0; j < 4; j++)
                upk2(acc2[i][j], r[2 * j], r[2 * j + 1]);
            float* op = out + (size_t)node * ROW_F + (size_t)c * H_DIM + tx * 8;
            *(float4*)(op)     = make_float4(r[0] + bias[0], r[1] + bias[1],
                                             r[2] + bias[2], r[3] + bias[3]);
            *(float4*)(op + 4) = make_float4(r[4] + bias[4], r[5] + bias[5],
                                             r[6] + bias[6], r[7] + bias[7]);
        }
    }
}

// ---------------------------------------------------------------------------
// Launch
// ---------------------------------------------------------------------------
extern "C" void kernel_launch(void* const* d_in, const int* in_sizes, int n_in,
                              void* d_out, int out_size) {
    const float* x      = (const float*)d_in[0];
    const void*  ei     = d_in[1];
    const float* Wsrel  = (const float*)d_in[2];
    const float* Wsroot = (const float*)d_in[3];
    const float* bsr    = (const float*)d_in[4];
    const float* Wvrel  = (const float*)d_in[5];
    const float* Wvroot = (const float*)d_in[6];
    float*       out    = (float*)d_out;

    const int smem_bytes = (KC * 128 + BM * ASTR) * sizeof(float);  // 67584
    cudaFuncSetAttribute(transform_kernel,
                         cudaFuncAttributeMaxDynamicSharedMemorySize, smem_bytes);

    // Phase 0: dtype detect + weight prep
    detect_dtype_kernel<<<1, 1>>>((const int*)ei);
    {
        dim3 grid(256, 4);
        prep_weights_kernel<<<grid, 128>>>(Wsrel, Wsroot, Wvrel, Wvroot);
    }

    // Phase 1: CSR build
    zero_cnt_kernel<<<(N_NODES + 255) / 256, 256>>>();
    hist_kernel<<<(E_EDGES + 255) / 256, 256>>>(ei);
    scan_kernel<<<1, 1024>>>();
    scatter_kernel<<<(E_EDGES + 255) / 256, 256>>>(ei);

    // Phase 2: CSR aggregation (2 nodes per 256-thread block)
    csr_agg_kernel<<<(N_NODES + 1) / 2, 256>>>(x);

    // Phase 3: transform
    {
        dim3 grid((N_NODES + BM - 1) / BM, 4);
        transform_kernel<<<grid, 256, smem_bytes>>>(x, bsr, out);
    }
}

// round 6
// speedup vs baseline: 3.6754x; 1.4156x over previous
#include <cuda_runtime.h>
#include <cuda_bf16.h>
#include <cstdint>

#define N_NODES 50000
#define E_EDGES 500000
#define H_DIM   128
#define ROW_F   512          // 4 channels * 128 floats per node

// ---------------------------------------------------------------------------
// Global scratch
// ---------------------------------------------------------------------------
__device__ float         g_agg[(size_t)N_NODES * ROW_F];
__device__ __nv_bfloat16 g_Whi[4 * 128 * 256];   // [c][n][k] hi halves
__device__ __nv_bfloat16 g_Wlo[4 * 128 * 256];   // [c][n][k] lo residuals
__device__ int g_is64;
__device__ int g_cnt[N_NODES];
__device__ int g_off[N_NODES + 1];
__device__ int g_cur[N_NODES];
__device__ int g_cols[E_EDGES];

// ---------------------------------------------------------------------------
// helpers
// ---------------------------------------------------------------------------
__device__ __forceinline__ uint32_t smem_u32(const void* p) {
    uint32_t a;
    asm("{ .reg .u64 t; cvta.to.shared.u64 t, %1; cvt.u32.u64 %0, t; }"
        : "=r"(a) : "l"(p));
    return a;
}

// pack two f32 into bf16x2 (lo arg -> low half, hi arg -> high half)
__device__ __forceinline__ uint32_t cvt_bf16x2(float lo, float hi) {
    uint32_t r;
    asm("cvt.rn.bf16x2.f32 %0, %1, %2;" : "=r"(r) : "f"(hi), "f"(lo));
    return r;
}

#define SW128(o) ((o) ^ (((o) >> 3) & 0x70))

__device__ __forceinline__ void ldsm_x4(uint32_t addr, uint32_t& r0, uint32_t& r1,
                                        uint32_t& r2, uint32_t& r3) {
    asm volatile("ldmatrix.sync.aligned.m8n8.x4.shared.b16 {%0,%1,%2,%3}, [%4];"
                 : "=r"(r0), "=r"(r1), "=r"(r2), "=r"(r3) : "r"(addr));
}

__device__ __forceinline__ void mma16816(float* c, const uint32_t* a,
                                         uint32_t b0, uint32_t b1) {
    asm volatile(
        "mma.sync.aligned.m16n8k16.row.col.f32.bf16.bf16.f32 "
        "{%0,%1,%2,%3}, {%4,%5,%6,%7}, {%8,%9}, {%0,%1,%2,%3};"
        : "+f"(c[0]), "+f"(c[1]), "+f"(c[2]), "+f"(c[3])
        : "r"(a[0]), "r"(a[1]), "r"(a[2]), "r"(a[3]), "r"(b0), "r"(b1));
}

// ---------------------------------------------------------------------------
// edge index fetch with dtype branch
// ---------------------------------------------------------------------------
__device__ __forceinline__ int edge_idx(const void* ei_raw, size_t i) {
    if (g_is64) return (int)((const long long*)ei_raw)[i];
    return ((const int*)ei_raw)[i];
}

__global__ void detect_dtype_kernel(const int* __restrict__ ei32) {
    int all_zero = 1;
    for (int i = 0; i < 128; i++) {
        if (ei32[2 * i + 1] != 0) { all_zero = 0; break; }
    }
    g_is64 = all_zero;
}

// ---------------------------------------------------------------------------
// Weight prep: split stacked weights into bf16 hi + lo residual, [c][n][k]
// ---------------------------------------------------------------------------
__global__ void prep_weights_kernel(const float* __restrict__ Wsrel,
                                    const float* __restrict__ Wsroot,
                                    const float* __restrict__ Wvrel,
                                    const float* __restrict__ Wvroot) {
    int n = blockIdx.x;
    int c = blockIdx.y;
    int k = threadIdx.x;
    const float* root = (c == 0) ? Wsroot : Wvroot;
    const float* rel  = (c == 0) ? Wsrel  : Wvrel;
    float w = (k < 128) ? __ldg(root + n * 128 + k)
                        : __ldg(rel  + n * 128 + (k - 128));
    __nv_bfloat16 h = __float2bfloat16(w);
    float hf = __bfloat162float(h);
    __nv_bfloat16 l = __float2bfloat16(w - hf);
    size_t o = ((size_t)(c * 128 + n)) * 256 + k;
    g_Whi[o] = h;
    g_Wlo[o] = l;
}

// ---------------------------------------------------------------------------
// CSR build
// ---------------------------------------------------------------------------
__global__ void zero_cnt_kernel() {
    int i = blockIdx.x * blockDim.x + threadIdx.x;
    if (i < N_NODES) g_cnt[i] = 0;
}

__global__ __launch_bounds__(256)
void hist_kernel(const void* __restrict__ ei_raw) {
    int e = blockIdx.x * blockDim.x + threadIdx.x;
    if (e < E_EDGES) atomicAdd(&g_cnt[edge_idx(ei_raw, e)], 1);
}

__global__ __launch_bounds__(1024)
void scan_kernel() {
    __shared__ int s[1024];
    __shared__ int carry_s;
    int tid = threadIdx.x;
    if (tid == 0) carry_s = 0;
    __syncthreads();
    for (int base = 0; base < N_NODES; base += 1024) {
        int i = base + tid;
        int v = (i < N_NODES) ? g_cnt[i] : 0;
        s[tid] = v;
        __syncthreads();
        #pragma unroll
        for (int d = 1; d < 1024; d <<= 1) {
            int t = (tid >= d) ? s[tid - d] : 0;
            __syncthreads();
            s[tid] += t;
            __syncthreads();
        }
        int excl = s[tid] - v;
        int carry = carry_s;
        if (i < N_NODES) {
            g_off[i] = carry + excl;
            g_cur[i] = carry + excl;
        }
        int total = s[1023];
        __syncthreads();
        if (tid == 0) carry_s = carry + total;
        __syncthreads();
    }
    if (tid == 0) g_off[N_NODES] = carry_s;
}

__global__ __launch_bounds__(256)
void scatter_kernel(const void* __restrict__ ei_raw) {
    int e = blockIdx.x * blockDim.x + threadIdx.x;
    if (e < E_EDGES) {
        int row = edge_idx(ei_raw, e);
        int col = edge_idx(ei_raw, (size_t)E_EDGES + e);
        int pos = atomicAdd(&g_cur[row], 1);
        g_cols[pos] = col;
    }
}

// ---------------------------------------------------------------------------
// CSR aggregation, unrolled x2 for gather MLP
// ---------------------------------------------------------------------------
__global__ __launch_bounds__(256)
void csr_agg_kernel(const float* __restrict__ x) {
    int node = blockIdx.x * 2 + (threadIdx.x >> 7);
    int lane = threadIdx.x & 127;
    if (node >= N_NODES) return;

    int beg = __ldg(&g_off[node]);
    int end = __ldg(&g_off[node + 1]);

    float4 a0 = make_float4(0.f, 0.f, 0.f, 0.f);
    float4 a1 = make_float4(0.f, 0.f, 0.f, 0.f);
    int j = beg;
    for (; j + 1 < end; j += 2) {
        int c0 = __ldg(&g_cols[j]);
        int c1 = __ldg(&g_cols[j + 1]);
        float4 v0 = __ldg((const float4*)(x + (size_t)c0 * ROW_F) + lane);
        float4 v1 = __ldg((const float4*)(x + (size_t)c1 * ROW_F) + lane);
        a0.x += v0.x; a0.y += v0.y; a0.z += v0.z; a0.w += v0.w;
        a1.x += v1.x; a1.y += v1.y; a1.z += v1.z; a1.w += v1.w;
    }
    if (j < end) {
        int c0 = __ldg(&g_cols[j]);
        float4 v0 = __ldg((const float4*)(x + (size_t)c0 * ROW_F) + lane);
        a0.x += v0.x; a0.y += v0.y; a0.z += v0.z; a0.w += v0.w;
    }
    a0.x += a1.x; a0.y += a1.y; a0.z += a1.z; a0.w += a1.w;
    ((float4*)(g_agg + (size_t)node * ROW_F))[lane] = a0;
}

// ---------------------------------------------------------------------------
// Transform: split-bf16 HMMA GEMM (mma.sync.m16n8k16).
//   Block 128 nodes x 128 outs, K=256 stacked [x | agg] per channel c,
//   chunked 4 x 64. 8 warps, warp tile 32m x 64n. 3 split MMAs per term pair.
// ---------------------------------------------------------------------------
#define SM_AHI 0
#define SM_ALO 16384
#define SM_WHI 32768
#define SM_WLO 49152
#define SM_TOTAL 65536

__global__ __launch_bounds__(256, 2)
void transform_mma_kernel(const float* __restrict__ x,
                          const float* __restrict__ bsr,
                          float* __restrict__ out) {
    extern __shared__ char smem[];
    const uint32_t sb = smem_u32(smem);
    const int tid  = threadIdx.x;
    const int wid  = tid >> 5;
    const int lane = tid & 31;
    const int c      = blockIdx.y;
    const int node0  = blockIdx.x * 128;
    const int warp_m = (wid & 3) * 32;   // 4 warps along m
    const int warp_n = (wid >> 2) * 64;  // 2 warps along n

    float acc[2][8][4];
    #pragma unroll
    for (int mt = 0; mt < 2; mt++)
        #pragma unroll
        for (int j = 0; j < 8; j++)
            #pragma unroll
            for (int q = 0; q < 4; q++) acc[mt][j][q] = 0.f;

    const float* agg = g_agg;

    // precompute ldmatrix lane-address components (byte offsets before swizzle)
    // A: row = warp_m + mt*16 + (lane&15), kbyte = ks*32 + (lane>>4)*16
    const int a_row_l = lane & 15;
    const int a_koff  = (lane >> 4) << 4;
    // B: row = warp_n + np*16 + ((lane>>4)<<3) + (lane&7), kbyte = ks*32 + ((lane>>3)&1)*16
    const int b_row_l = ((lane >> 4) << 3) + (lane & 7);
    const int b_koff  = ((lane >> 3) & 1) << 4;

    for (int kc = 0; kc < 4; kc++) {
        // ---- A chunk: 128 nodes x 64 k, fp32 -> hi/lo bf16, SW128 ----
        {
            const float* src = (kc < 2) ? x : agg;
            const int koff = (kc & 1) * 64 + c * H_DIM;
            #pragma unroll
            for (int it = 0; it < 8; it++) {
                int idx = tid + it * 256;        // 0..2047
                int q = idx & 15;                // float4 within 64-float row
                int m = idx >> 4;                // node row
                int node = node0 + m;
                float4 v = make_float4(0.f, 0.f, 0.f, 0.f);
                if (node < N_NODES)
                    v = __ldg((const float4*)(src + (size_t)node * ROW_F + koff) + q);

                float hx = __bfloat162float(__float2bfloat16(v.x));
                float hy = __bfloat162float(__float2bfloat16(v.y));
                float hz = __bfloat162float(__float2bfloat16(v.z));
                float hw = __bfloat162float(__float2bfloat16(v.w));

                uint2 hi = make_uint2(cvt_bf16x2(v.x, v.y), cvt_bf16x2(v.z, v.w));
                uint2 lo = make_uint2(cvt_bf16x2(v.x - hx, v.y - hy),
                                      cvt_bf16x2(v.z - hz, v.w - hw));

                uint32_t boff = (uint32_t)(m * 128 + q * 8);
                uint32_t sw = SW128(boff);
                *(uint2*)(smem + SM_AHI + sw) = hi;
                *(uint2*)(smem + SM_ALO + sw) = lo;
            }
        }
        // ---- W chunk: 128 outs x 64 k bf16 hi/lo, SW128 ----
        {
            const size_t kbase = (size_t)(c * 128) * 256 + kc * 64;
            #pragma unroll
            for (int it = 0; it < 4; it++) {
                int idx = tid + it * 256;        // 0..1023
                int u = idx & 7;                 // 16B unit within 128B row
                int n = idx >> 3;                // output row
                const uint4* ph = (const uint4*)(g_Whi + kbase + (size_t)n * 256);
                const uint4* pl = (const uint4*)(g_Wlo + kbase + (size_t)n * 256);
                uint4 vh = __ldg(ph + u);
                uint4 vl = __ldg(pl + u);
                uint32_t boff = (uint32_t)(n * 128 + u * 16);
                uint32_t sw = SW128(boff);
                *(uint4*)(smem + SM_WHI + sw) = vh;
                *(uint4*)(smem + SM_WLO + sw) = vl;
            }
        }
        __syncthreads();

        // ---- compute: 4 k16-steps ----
        #pragma unroll
        for (int ks = 0; ks < 4; ks++) {
            uint32_t ah[2][4], al[2][4];
            #pragma unroll
            for (int mt = 0; mt < 2; mt++) {
                uint32_t boff = (uint32_t)((warp_m + mt * 16 + a_row_l) * 128
                                           + ks * 32 + a_koff);
                uint32_t sw = SW128(boff);
                ldsm_x4(sb + SM_AHI + sw, ah[mt][0], ah[mt][1], ah[mt][2], ah[mt][3]);
                ldsm_x4(sb + SM_ALO + sw, al[mt][0], al[mt][1], al[mt][2], al[mt][3]);
            }
            #pragma unroll
            for (int np = 0; np < 4; np++) {
                uint32_t boff = (uint32_t)((warp_n + np * 16 + b_row_l) * 128
                                           + ks * 32 + b_koff);
                uint32_t sw = SW128(boff);
                uint32_t bh0, bh1, bh2, bh3, bl0, bl1, bl2, bl3;
                ldsm_x4(sb + SM_WHI + sw, bh0, bh1, bh2, bh3);
                ldsm_x4(sb + SM_WLO + sw, bl0, bl1, bl2, bl3);
                #pragma unroll
                for (int mt = 0; mt < 2; mt++) {
                    mma16816(acc[mt][np * 2 + 0], ah[mt], bh0, bh1);
                    mma16816(acc[mt][np * 2 + 0], al[mt], bh0, bh1);
                    mma16816(acc[mt][np * 2 + 0], ah[mt], bl0, bl1);
                    mma16816(acc[mt][np * 2 + 1], ah[mt], bh2, bh3);
                    mma16816(acc[mt][np * 2 + 1], al[mt], bh2, bh3);
                    mma16816(acc[mt][np * 2 + 1], ah[mt], bl2, bl3);
                }
            }
        }
        __syncthreads();
    }

    // ---- epilogue: fragment (m16n8) c0,c1 at (row=lane/4, col=2*(lane%4)),
    //      c2,c3 at row+8 ----
    const int erow = lane >> 2;
    const int ecol = (lane & 3) * 2;
    #pragma unroll
    for (int mt = 0; mt < 2; mt++) {
        #pragma unroll
        for (int j = 0; j < 8; j++) {
            int col = warp_n + j * 8 + ecol;
            float b0 = 0.f, b1 = 0.f;
            if (c == 0) { b0 = __ldg(bsr + col); b1 = __ldg(bsr + col + 1); }
            int r0 = node0 + warp_m + mt * 16 + erow;
            int r1 = r0 + 8;
            if (r0 < N_NODES) {
                float2 v = make_float2(acc[mt][j][0] + b0, acc[mt][j][1] + b1);
                *(float2*)(out + (size_t)r0 * ROW_F + (size_t)c * H_DIM + col) = v;
            }
            if (r1 < N_NODES) {
                float2 v = make_float2(acc[mt][j][2] + b0, acc[mt][j][3] + b1);
                *(float2*)(out + (size_t)r1 * ROW_F + (size_t)c * H_DIM + col) = v;
            }
        }
    }
}

// ---------------------------------------------------------------------------
// Launch
// ---------------------------------------------------------------------------
extern "C" void kernel_launch(void* const* d_in, const int* in_sizes, int n_in,
                              void* d_out, int out_size) {
    const float* x      = (const float*)d_in[0];
    const void*  ei     = d_in[1];
    const float* Wsrel  = (const float*)d_in[2];
    const float* Wsroot = (const float*)d_in[3];
    const float* bsr    = (const float*)d_in[4];
    const float* Wvrel  = (const float*)d_in[5];
    const float* Wvroot = (const float*)d_in[6];
    float*       out    = (float*)d_out;

    cudaFuncSetAttribute(transform_mma_kernel,
                         cudaFuncAttributeMaxDynamicSharedMemorySize, SM_TOTAL);

    // Phase 0: dtype detect + weight split
    detect_dtype_kernel<<<1, 1>>>((const int*)ei);
    {
        dim3 grid(128, 4);
        prep_weights_kernel<<<grid, 256>>>(Wsrel, Wsroot, Wvrel, Wvroot);
    }

    // Phase 1: CSR build
    zero_cnt_kernel<<<(N_NODES + 255) / 256, 256>>>();
    hist_kernel<<<(E_EDGES + 255) / 256, 256>>>(ei);
    scan_kernel<<<1, 1024>>>();
    scatter_kernel<<<(E_EDGES + 255) / 256, 256>>>(ei);

    // Phase 2: CSR aggregation
    csr_agg_kernel<<<(N_NODES + 1) / 2, 256>>>(x);

    // Phase 3: transform (split-bf16 HMMA)
    {
        dim3 grid((N_NODES + 127) / 128, 4);
        transform_mma_kernel<<<grid, 256, SM_TOTAL>>>(x, bsr, out);
    }
}